// round 15
// baseline (speedup 1.0000x reference)
#include <cuda_runtime.h>

// OpenLSTM: B=4096 sequences, T=1024, HID=16, PROJ=2.
// t < 256 teacher-forced; t >= 256 recurrent.
//
// R15 = R14 (184.8us best) with the teacher phase switched to the segregated
// 4-SHFL reduction (teacher is MIO-throughput-bound; 13->9 MIO ops/warp-step)
// + 2-lane predicated scalar stores (lane0 -> h.x, lane8 -> h.y; distinct
// addresses, no BSSY, no same-address replay). One xor-8 broadcast at the
// phase boundary only. Recurrent phase byte-identical to R14 (pred stores,
// hc-trick, RU=4 block unroll).
// Layout: TPE=16, 2 elem/warp, 2048 warps (3.46/SMSP). Folded sigmoids.

#define T_TOTAL 1024
#define N_CTX   256
#define TPE     16
#define EPB     4     // elements per 64-thread block
#define TU      4     // teacher-phase time unroll
#define RU      4     // recurrent block unroll

__device__ __forceinline__ float tanh_fast(float x) {
    float y;
    asm("tanh.approx.f32 %0, %1;" : "=f"(y) : "f"(x));
    return y;
}

// Predicated 8-byte store (no BSSY/BSYNC): if (j==0) st.v2 [addr]
__device__ __forceinline__ void store2_if(int j, float2* addr, float a, float b) {
    asm volatile(
        "{ .reg .pred p; setp.eq.s32 p, %0, 0; @p st.global.v2.f32 [%1], {%2, %3}; }"
        :: "r"(j), "l"(addr), "f"(a), "f"(b) : "memory");
}

// Predicated 4-byte store: if (pred32 == 0) st.f32 [addr]
__device__ __forceinline__ void store1_if(int pred32, float* addr, float a) {
    asm volatile(
        "{ .reg .pred p; setp.eq.s32 p, %0, 0; @p st.global.f32 [%1], %2; }"
        :: "r"(pred32), "l"(addr), "f"(a) : "memory");
}

__global__ void __launch_bounds__(64)
open_lstm_kernel(const float* __restrict__ u,     // (B, T, 4)
                 const float* __restrict__ w_ih,  // (64, 2)
                 const float* __restrict__ w_hh,  // (64, 2)
                 const float* __restrict__ b_ih,  // (64)
                 const float* __restrict__ b_hh,  // (64)
                 const float* __restrict__ w_hr,  // (2, 16)
                 float* __restrict__ out)         // (B, T, 2)
{
    const int tid  = threadIdx.x;
    const int j    = tid & (TPE - 1);                 // hidden unit 0..15
    const int e    = blockIdx.x * EPB + (tid >> 4);   // element index
    const bool lo8 = (j < 8);
    const int  jm8 = j & 7;                           // 0 only for lanes 0 and 8
    const int  so  = (j >> 3) & 1;                    // 0 -> h.x slot, 1 -> h.y slot

    // Weights for unit j. sigma(x)=0.5*tanh(0.5x)+0.5 folded: i/f/o gate rows
    // pre-scaled by 0.5; o-path outer 0.5 folded into w_hr.
    float wi[4][2], wh[4][2], bb[4], wr0, wr1;
#pragma unroll
    for (int k = 0; k < 4; k++) {
        const int r = k * 16 + j;
        const float sc = (k == 2) ? 1.0f : 0.5f;
        wi[k][0] = w_ih[r * 2 + 0] * sc;
        wi[k][1] = w_ih[r * 2 + 1] * sc;
        wh[k][0] = w_hh[r * 2 + 0] * sc;
        wh[k][1] = w_hh[r * 2 + 1] * sc;
        bb[k]    = (b_ih[r] + b_hh[r]) * sc;
    }
    wr0 = w_hr[j]      * 0.5f;
    wr1 = w_hr[16 + j] * 0.5f;

    const float4* __restrict__ up = (const float4*)u + (size_t)e * T_TOTAL;
    float2* __restrict__ op       = (float2*)out + (size_t)e * T_TOTAL;
    float* __restrict__ opf       = (float*)op;

    float hc = 0.0f;               // c/2 (state)
    float h0 = 0.0f, h1 = 0.0f;

    // ======== teacher-forced phase: segregated 4-SHFL reduce, unrolled x4 ====
    float rlast = 0.0f;            // segregated h (h0 on lanes<8, h1 on lanes>=8)
#pragma unroll 1
    for (int t = 0; t < N_CTX; t += TU) {
        float4 vv[TU];
#pragma unroll
        for (int s = 0; s < TU; s++) vv[s] = up[t + s];

        float gg[TU][4];
#pragma unroll
        for (int s = 0; s < TU; s++)
#pragma unroll
            for (int k = 0; k < 4; k++)
                gg[s][k] = fmaf(wi[k][0], vv[s].x,
                           fmaf(wi[k][1], vv[s].y,
                           fmaf(wh[k][0], vv[s].z,
                           fmaf(wh[k][1], vv[s].w, bb[k]))));

        float ti[TU], tf[TU], tg[TU], to[TU];
#pragma unroll
        for (int s = 0; s < TU; s++) {
            ti[s] = tanh_fast(gg[s][0]);
            tf[s] = tanh_fast(gg[s][1]);
            tg[s] = tanh_fast(gg[s][2]);
            to[s] = tanh_fast(gg[s][3]);
        }

        float tc[TU];
#pragma unroll
        for (int s = 0; s < TU; s++) {
            float ca = fmaf(tf[s], hc, hc);          // sigma(f)*c
            float cb = fmaf(ti[s], tg[s], tg[s]);    // 2*sigma(i)*tanh(g)
            float cf = fmaf(0.5f, cb, ca);           // new c
            tc[s] = tanh_fast(cf);
            hc = 0.5f * cf;                          // off-chain state update
        }

        float rr[TU];
#pragma unroll
        for (int s = 0; s < TU; s++) {
            float b0 = fmaf(wr0, to[s], wr0);        // wr0*(1+to)
            float b1 = fmaf(wr1, to[s], wr1);
            float p0 = b0 * tc[s];
            float p1 = b1 * tc[s];
            // segregate: lanes<8 accumulate p0, lanes>=8 accumulate p1
            float send = lo8 ? p1 : p0;
            float keep = lo8 ? p0 : p1;
            float r = keep + __shfl_xor_sync(0xffffffffu, send, 8);
            r += __shfl_xor_sync(0xffffffffu, r, 1);
            r += __shfl_xor_sync(0xffffffffu, r, 2);
            r += __shfl_xor_sync(0xffffffffu, r, 4);
            rr[s] = r;
        }
        // 2-lane predicated scalar stores: lane0 -> h.x, lane8 -> h.y
#pragma unroll
        for (int s = 0; s < TU; s++)
            store1_if(jm8, opf + 2 * (t + s) + so, rr[s]);
        rlast = rr[TU - 1];
    }

    // phase boundary: single broadcast of final teacher h into all lanes
    {
        float o2 = __shfl_xor_sync(0xffffffffu, rlast, 8);
        h0 = lo8 ? rlast : o2;
        h1 = lo8 ? o2 : rlast;
    }

    // ================= recurrent phase (byte-identical to R14) ===============
    float xp[4];
    {
        float4 v0 = up[N_CTX];
#pragma unroll
        for (int k = 0; k < 4; k++)
            xp[k] = fmaf(wi[k][0], v0.x, fmaf(wi[k][1], v0.y, bb[k]));
    }

#pragma unroll 1
    for (int t = N_CTX; t < T_TOTAL - RU; t += RU) {
        float4 vn[RU];
#pragma unroll
        for (int s = 0; s < RU; s++) vn[s] = up[t + 1 + s];

        float xpn[RU][4];
#pragma unroll
        for (int s = 0; s < RU; s++)
#pragma unroll
            for (int k = 0; k < 4; k++)
                xpn[s][k] = fmaf(wi[k][0], vn[s].x,
                            fmaf(wi[k][1], vn[s].y, bb[k]));

#pragma unroll
        for (int s = 0; s < RU; s++) {
            const float* xps = (s == 0) ? xp : xpn[s - 1];

            float gi  = fmaf(wh[0][0], h0, fmaf(wh[0][1], h1, xps[0]));
            float gf  = fmaf(wh[1][0], h0, fmaf(wh[1][1], h1, xps[1]));
            float gg2 = fmaf(wh[2][0], h0, fmaf(wh[2][1], h1, xps[2]));
            float go  = fmaf(wh[3][0], h0, fmaf(wh[3][1], h1, xps[3]));

            float ti = tanh_fast(gi);
            float tf = tanh_fast(gf);
            float tg = tanh_fast(gg2);
            float to = tanh_fast(go);

            float ca = fmaf(tf, hc, hc);             // sigma(f)*c
            float cb = fmaf(ti, tg, tg);             // 2*sigma(i)*tanh(g)
            float cf = fmaf(0.5f, cb, ca);           // new c
            float tc = tanh_fast(cf);
            hc = 0.5f * cf;                          // off-chain

            float b0 = fmaf(wr0, to, wr0);           // off-chain during tanh
            float b1 = fmaf(wr1, to, wr1);

            float p0 = b0 * tc;
            float p1 = b1 * tc;
#pragma unroll
            for (int k = 1; k < TPE; k <<= 1) {
                p0 += __shfl_xor_sync(0xffffffffu, p0, k, TPE);
                p1 += __shfl_xor_sync(0xffffffffu, p1, k, TPE);
            }
            h0 = p0; h1 = p1;
            store2_if(j, op + (t + s), p0, p1);
        }
#pragma unroll
        for (int k = 0; k < 4; k++) xp[k] = xpn[RU - 1][k];
    }

    // -------- epilogue: last RU steps, clamped prefetch --------
#pragma unroll 1
    for (int t = T_TOTAL - RU; t < T_TOTAL; t++) {
        float4 vn = up[(t + 1 < T_TOTAL) ? (t + 1) : t];

        float gi  = fmaf(wh[0][0], h0, fmaf(wh[0][1], h1, xp[0]));
        float gf  = fmaf(wh[1][0], h0, fmaf(wh[1][1], h1, xp[1]));
        float gg2 = fmaf(wh[2][0], h0, fmaf(wh[2][1], h1, xp[2]));
        float go  = fmaf(wh[3][0], h0, fmaf(wh[3][1], h1, xp[3]));

        float ti = tanh_fast(gi);
        float tf = tanh_fast(gf);
        float tg = tanh_fast(gg2);
        float to = tanh_fast(go);

        float ca = fmaf(tf, hc, hc);
        float cb = fmaf(ti, tg, tg);
        float cf = fmaf(0.5f, cb, ca);
        float tc = tanh_fast(cf);
        hc = 0.5f * cf;

        float b0 = fmaf(wr0, to, wr0);
        float b1 = fmaf(wr1, to, wr1);

        float p0 = b0 * tc;
        float p1 = b1 * tc;
#pragma unroll
        for (int k = 1; k < TPE; k <<= 1) {
            p0 += __shfl_xor_sync(0xffffffffu, p0, k, TPE);
            p1 += __shfl_xor_sync(0xffffffffu, p1, k, TPE);
        }
        h0 = p0; h1 = p1;
        store2_if(j, op + t, p0, p1);

#pragma unroll
        for (int k = 0; k < 4; k++)
            xp[k] = fmaf(wi[k][0], vn.x, fmaf(wi[k][1], vn.y, bb[k]));
    }
}

extern "C" void kernel_launch(void* const* d_in, const int* in_sizes, int n_in,
                              void* d_out, int out_size)
{
    const float* u    = (const float*)d_in[0];
    const float* w_ih = (const float*)d_in[1];
    const float* w_hh = (const float*)d_in[2];
    const float* b_ih = (const float*)d_in[3];
    const float* b_hh = (const float*)d_in[4];
    const float* w_hr = (const float*)d_in[5];
    float* out = (float*)d_out;

    const int B = in_sizes[0] / (T_TOTAL * 4);   // 4096
    const int grid = B / EPB;                    // 1024 blocks x 64 threads

    open_lstm_kernel<<<grid, 64>>>(u, w_ih, w_hh, b_ih, b_hh, w_hr, out);
}